// round 1
// baseline (speedup 1.0000x reference)
#include <cuda_runtime.h>
#include <cuda_fp16.h>
#include <cstdint>

#define B_  2
#define H_  12
#define S_  2048
#define D_  64
#define BM  64
#define BN  64
#define LDK 72   // padded half stride (avoids smem bank conflicts)

__device__ __forceinline__ float ex2f(float x) {
    float y;
    asm("ex2.approx.ftz.f32 %0, %1;" : "=f"(y) : "f"(x));
    return y;
}

__device__ __forceinline__ uint32_t pack2(__half a, __half b) {
    __half2 h = __halves2half2(a, b);
    return *reinterpret_cast<uint32_t*>(&h);
}

__device__ __forceinline__ void hsplit(float x, __half& hi, __half& lo) {
    hi = __float2half_rn(x);
    lo = __float2half_rn(x - __half2float(hi));
}

// D += A * B  (m16n8k16, f16 inputs, f32 accumulate)
__device__ __forceinline__ void mma16816(float d[4], const uint32_t a[4],
                                         uint32_t b0, uint32_t b1) {
    asm volatile(
        "mma.sync.aligned.m16n8k16.row.col.f32.f16.f16.f32 "
        "{%0,%1,%2,%3}, {%4,%5,%6,%7}, {%8,%9}, {%0,%1,%2,%3};\n"
        : "+f"(d[0]), "+f"(d[1]), "+f"(d[2]), "+f"(d[3])
        : "r"(a[0]), "r"(a[1]), "r"(a[2]), "r"(a[3]), "r"(b0), "r"(b1));
}

__global__ __launch_bounds__(128)
void fa_kernel(const float* __restrict__ q, const float* __restrict__ k,
               const float* __restrict__ v, const float* __restrict__ mask,
               float* __restrict__ out)
{
    __shared__ __half Kh_s[BN][LDK];   // K hi, [kv_row][d]
    __shared__ __half Kl_s[BN][LDK];   // K lo
    __shared__ __half Vt_s[D_][LDK];   // V transposed, [d][kv_row]

    const int bh   = blockIdx.x;     // 0..23
    const int qb   = blockIdx.y;     // 0..31
    const int b    = bh / H_;
    const int tid  = threadIdx.x;
    const int warp = tid >> 5;
    const int lane = tid & 31;
    const int g    = lane >> 2;      // groupID (row within 8)
    const int t    = lane & 3;       // threadID in group (col pair)

    const int qrow = qb * BM + warp * 16 + g;    // local q row (second row: +8)
    const float* qbase = q + ((size_t)bh * S_ + qrow) * D_;

    // ---- Q fragments (hi/lo fp16 split), resident for whole kernel ----
    uint32_t Ah[4][4], Al[4][4];
#pragma unroll
    for (int kt = 0; kt < 4; ++kt) {
#pragma unroll
        for (int rr = 0; rr < 2; ++rr) {       // row g / g+8
#pragma unroll
            for (int hh = 0; hh < 2; ++hh) {   // k offset 0 / +8
                const float* p = qbase + rr * 8 * D_ + kt * 16 + hh * 8 + 2 * t;
                float2 x = *reinterpret_cast<const float2*>(p);
                __half hx, lx, hy, ly;
                hsplit(x.x, hx, lx);
                hsplit(x.y, hy, ly);
                int reg = rr + hh * 2;   // a0,a1,a2,a3 ordering
                Ah[kt][reg] = pack2(hx, hy);
                Al[kt][reg] = pack2(lx, ly);
            }
        }
    }

    float oA[8][4];
#pragma unroll
    for (int jd = 0; jd < 8; ++jd)
#pragma unroll
        for (int i = 0; i < 4; ++i) oA[jd][i] = 0.f;

    float mrun0 = -1e30f, mrun1 = -1e30f, lrun0 = 0.f, lrun1 = 0.f;

    const float* kbase = k + (size_t)bh * S_ * D_;
    const float* vbase = v + (size_t)bh * S_ * D_;
    const float* mbase = mask + (size_t)b * S_ * S_ + (size_t)qrow * S_;

    const float L2E = 1.4426950408889634f;

    for (int jb = 0; jb < S_ / BN; ++jb) {
        // ---- cooperative load K (hi/lo split) and V (transposed) ----
#pragma unroll
        for (int i = 0; i < 8; ++i) {
            int idx = tid + i * 128;            // 0..1023
            int row = idx >> 4;
            int c4  = (idx & 15) * 4;
            const float4 kx = *reinterpret_cast<const float4*>(
                kbase + ((size_t)(jb * BN + row)) * D_ + c4);
            const float4 vx = *reinterpret_cast<const float4*>(
                vbase + ((size_t)(jb * BN + row)) * D_ + c4);

            __half h0, l0, h1, l1, h2, l2, h3, l3;
            hsplit(kx.x, h0, l0); hsplit(kx.y, h1, l1);
            hsplit(kx.z, h2, l2); hsplit(kx.w, h3, l3);
            *reinterpret_cast<uint32_t*>(&Kh_s[row][c4])     = pack2(h0, h1);
            *reinterpret_cast<uint32_t*>(&Kh_s[row][c4 + 2]) = pack2(h2, h3);
            *reinterpret_cast<uint32_t*>(&Kl_s[row][c4])     = pack2(l0, l1);
            *reinterpret_cast<uint32_t*>(&Kl_s[row][c4 + 2]) = pack2(l2, l3);

            Vt_s[c4 + 0][row] = __float2half_rn(vx.x);
            Vt_s[c4 + 1][row] = __float2half_rn(vx.y);
            Vt_s[c4 + 2][row] = __float2half_rn(vx.z);
            Vt_s[c4 + 3][row] = __float2half_rn(vx.w);
        }
        __syncthreads();

        // ---- S = Q K^T in 3 fp16 split-GEMMs (fp32 accurate) ----
        float sA[8][4];
#pragma unroll
        for (int j8 = 0; j8 < 8; ++j8)
#pragma unroll
            for (int i = 0; i < 4; ++i) sA[j8][i] = 0.f;

#pragma unroll
        for (int j8 = 0; j8 < 8; ++j8) {
            const int n = j8 * 8 + g;
#pragma unroll
            for (int kt = 0; kt < 4; ++kt) {
                uint32_t bh0 = *reinterpret_cast<const uint32_t*>(&Kh_s[n][kt * 16 + 2 * t]);
                uint32_t bh1 = *reinterpret_cast<const uint32_t*>(&Kh_s[n][kt * 16 + 2 * t + 8]);
                uint32_t bl0 = *reinterpret_cast<const uint32_t*>(&Kl_s[n][kt * 16 + 2 * t]);
                uint32_t bl1 = *reinterpret_cast<const uint32_t*>(&Kl_s[n][kt * 16 + 2 * t + 8]);
                mma16816(sA[j8], Ah[kt], bh0, bh1);   // qh*kh
                mma16816(sA[j8], Al[kt], bh0, bh1);   // ql*kh
                mma16816(sA[j8], Ah[kt], bl0, bl1);   // qh*kl
            }
        }

        // ---- additive mask (direct from gmem, L2-resident) ----
        const float* m0p = mbase + jb * BN;
#pragma unroll
        for (int j8 = 0; j8 < 8; ++j8) {
            float2 m0 = *reinterpret_cast<const float2*>(m0p + j8 * 8 + 2 * t);
            float2 m1 = *reinterpret_cast<const float2*>(m0p + (size_t)8 * S_ + j8 * 8 + 2 * t);
            sA[j8][0] += m0.x; sA[j8][1] += m0.y;
            sA[j8][2] += m1.x; sA[j8][3] += m1.y;
        }

        // ---- online softmax ----
        float rm0 = -1e30f, rm1 = -1e30f;
#pragma unroll
        for (int j8 = 0; j8 < 8; ++j8) {
            rm0 = fmaxf(rm0, fmaxf(sA[j8][0], sA[j8][1]));
            rm1 = fmaxf(rm1, fmaxf(sA[j8][2], sA[j8][3]));
        }
        rm0 = fmaxf(rm0, __shfl_xor_sync(0xffffffffu, rm0, 1));
        rm0 = fmaxf(rm0, __shfl_xor_sync(0xffffffffu, rm0, 2));
        rm1 = fmaxf(rm1, __shfl_xor_sync(0xffffffffu, rm1, 1));
        rm1 = fmaxf(rm1, __shfl_xor_sync(0xffffffffu, rm1, 2));

        float mn0 = fmaxf(mrun0, rm0), mn1 = fmaxf(mrun1, rm1);
        float al0 = ex2f((mrun0 - mn0) * L2E);
        float al1 = ex2f((mrun1 - mn1) * L2E);
        mrun0 = mn0; mrun1 = mn1;

        float rs0 = 0.f, rs1 = 0.f;
        uint32_t Pa[4][4];
#pragma unroll
        for (int j8 = 0; j8 < 8; ++j8) {
            float p0 = ex2f((sA[j8][0] - mn0) * L2E);
            float p1 = ex2f((sA[j8][1] - mn0) * L2E);
            float p2 = ex2f((sA[j8][2] - mn1) * L2E);
            float p3 = ex2f((sA[j8][3] - mn1) * L2E);
            rs0 += p0 + p1;
            rs1 += p2 + p3;
            uint32_t h01 = pack2(__float2half_rn(p0), __float2half_rn(p1));
            uint32_t h23 = pack2(__float2half_rn(p2), __float2half_rn(p3));
            Pa[j8 >> 1][(j8 & 1) * 2 + 0] = h01;
            Pa[j8 >> 1][(j8 & 1) * 2 + 1] = h23;
        }
        rs0 += __shfl_xor_sync(0xffffffffu, rs0, 1);
        rs0 += __shfl_xor_sync(0xffffffffu, rs0, 2);
        rs1 += __shfl_xor_sync(0xffffffffu, rs1, 1);
        rs1 += __shfl_xor_sync(0xffffffffu, rs1, 2);
        lrun0 = lrun0 * al0 + rs0;
        lrun1 = lrun1 * al1 + rs1;

#pragma unroll
        for (int jd = 0; jd < 8; ++jd) {
            oA[jd][0] *= al0; oA[jd][1] *= al0;
            oA[jd][2] *= al1; oA[jd][3] *= al1;
        }

        // ---- O += P V (fp16, fp32 accum) ----
#pragma unroll
        for (int jd = 0; jd < 8; ++jd) {
            const int n = jd * 8 + g;
#pragma unroll
            for (int kt2 = 0; kt2 < 4; ++kt2) {
                uint32_t b0 = *reinterpret_cast<const uint32_t*>(&Vt_s[n][kt2 * 16 + 2 * t]);
                uint32_t b1 = *reinterpret_cast<const uint32_t*>(&Vt_s[n][kt2 * 16 + 2 * t + 8]);
                mma16816(oA[jd], Pa[kt2], b0, b1);
            }
        }
        __syncthreads();
    }

    // ---- epilogue ----
    float i0 = 1.f / lrun0, i1 = 1.f / lrun1;
    float* obase = out + ((size_t)bh * S_ + qrow) * D_;
#pragma unroll
    for (int jd = 0; jd < 8; ++jd) {
        float2 w0, w1;
        w0.x = oA[jd][0] * i0; w0.y = oA[jd][1] * i0;
        w1.x = oA[jd][2] * i1; w1.y = oA[jd][3] * i1;
        *reinterpret_cast<float2*>(obase + jd * 8 + 2 * t) = w0;
        *reinterpret_cast<float2*>(obase + (size_t)8 * D_ + jd * 8 + 2 * t) = w1;
    }
}

extern "C" void kernel_launch(void* const* d_in, const int* in_sizes, int n_in,
                              void* d_out, int out_size) {
    (void)in_sizes; (void)n_in; (void)out_size;
    const float* q    = (const float*)d_in[0];
    const float* k    = (const float*)d_in[1];
    const float* v    = (const float*)d_in[2];
    const float* mask = (const float*)d_in[3];
    dim3 grid(B_ * H_, S_ / BM);
    fa_kernel<<<grid, 128>>>(q, k, v, mask, (float*)d_out);
}

// round 3
// speedup vs baseline: 1.7003x; 1.7003x over previous
#include <cuda_runtime.h>
#include <cuda_fp16.h>
#include <cstdint>

#define B_  2
#define H_  12
#define S_  2048
#define D_  64
#define BM  64
#define BN  64
#define NT  (S_ / BN)

__device__ __forceinline__ float ex2f(float x) {
    float y;
    asm("ex2.approx.ftz.f32 %0, %1;" : "=f"(y) : "f"(x));
    return y;
}

__device__ __forceinline__ uint32_t pack2(__half a, __half b) {
    __half2 h = __halves2half2(a, b);
    return *reinterpret_cast<uint32_t*>(&h);
}

__device__ __forceinline__ void hsplit(float x, __half& hi, __half& lo) {
    hi = __float2half_rn(x);
    lo = __float2half_rn(x - __half2float(hi));
}

__device__ __forceinline__ uint32_t s2u(const void* p) {
    uint32_t a;
    asm("{ .reg .u64 t; cvta.to.shared.u64 t, %1; cvt.u32.u64 %0, t; }" : "=r"(a) : "l"(p));
    return a;
}

// D += A * B  (m16n8k16, f16 in, f32 acc)
__device__ __forceinline__ void mma16816(float d[4], const uint32_t a[4],
                                         uint32_t b0, uint32_t b1) {
    asm volatile(
        "mma.sync.aligned.m16n8k16.row.col.f32.f16.f16.f32 "
        "{%0,%1,%2,%3}, {%4,%5,%6,%7}, {%8,%9}, {%0,%1,%2,%3};\n"
        : "+f"(d[0]), "+f"(d[1]), "+f"(d[2]), "+f"(d[3])
        : "r"(a[0]), "r"(a[1]), "r"(a[2]), "r"(a[3]), "r"(b0), "r"(b1));
}

__device__ __forceinline__ void ldm_x4(uint32_t r[4], uint32_t addr) {
    asm volatile("ldmatrix.sync.aligned.m8n8.x4.shared.b16 {%0,%1,%2,%3}, [%4];"
                 : "=r"(r[0]), "=r"(r[1]), "=r"(r[2]), "=r"(r[3]) : "r"(addr));
}

__device__ __forceinline__ void ldm_x4_t(uint32_t r[4], uint32_t addr) {
    asm volatile("ldmatrix.sync.aligned.m8n8.x4.trans.shared.b16 {%0,%1,%2,%3}, [%4];"
                 : "=r"(r[0]), "=r"(r[1]), "=r"(r[2]), "=r"(r[3]) : "r"(addr));
}

// XOR-swizzled address into a [64][64]-half tile (128B rows, 16B-block swizzle)
__device__ __forceinline__ uint32_t swaddr(uint32_t base, int row, int byteoff) {
    uint32_t blk = ((uint32_t)byteoff >> 4) ^ ((uint32_t)row & 7);
    return base + (uint32_t)row * 128u + (blk << 4) + ((uint32_t)byteoff & 15u);
}

// ldmatrix address for K tile: matrix rows = n, 16B col block = k
__device__ __forceinline__ uint32_t kaddr(uint32_t base, int nbase, int kbase, int lane) {
    int r = lane & 7;
    int n = nbase + ((lane >> 4) << 3) + r;
    int kcol = kbase + ((lane >> 3) & 1) * 8;
    return swaddr(base, n, kcol * 2);
}

// ldmatrix(.trans) address for V tile: rows = n, cols = d
__device__ __forceinline__ uint32_t vaddr(uint32_t base, int nbase, int dbase, int lane) {
    int r = lane & 7;
    int n = nbase + ((lane >> 3) & 1) * 8 + r;
    int d = dbase + ((lane >> 4) << 3);
    return swaddr(base, n, d * 2);
}

struct Smem {
    __half Kh[2][BN][64];
    __half Kl[2][BN][64];
    __half Vr[2][BN][64];
};

__global__ __launch_bounds__(128, 3)
void fa_kernel(const float* __restrict__ q, const float* __restrict__ k,
               const float* __restrict__ v, const float* __restrict__ mask,
               float* __restrict__ out)
{
    __shared__ Smem sm;

    const int bh   = blockIdx.x;
    const int qb   = blockIdx.y;
    const int b    = bh / H_;
    const int tid  = threadIdx.x;
    const int warp = tid >> 5;
    const int lane = tid & 31;
    const int g    = lane >> 2;
    const int t    = lane & 3;

    const uint32_t khb[2] = { s2u(&sm.Kh[0][0][0]), s2u(&sm.Kh[1][0][0]) };
    const uint32_t klb[2] = { s2u(&sm.Kl[0][0][0]), s2u(&sm.Kl[1][0][0]) };
    const uint32_t vrb[2] = { s2u(&sm.Vr[0][0][0]), s2u(&sm.Vr[1][0][0]) };

    const int qrow = qb * BM + warp * 16 + g;
    const float* qbase = q + ((size_t)bh * S_ + qrow) * D_;

    // ---- Q fragments (hi/lo fp16 split), resident ----
    uint32_t Ah[4][4], Al[4][4];
#pragma unroll
    for (int kt = 0; kt < 4; ++kt) {
#pragma unroll
        for (int rr = 0; rr < 2; ++rr) {
#pragma unroll
            for (int hh = 0; hh < 2; ++hh) {
                const float* p = qbase + rr * 8 * D_ + kt * 16 + hh * 8 + 2 * t;
                float2 x = *reinterpret_cast<const float2*>(p);
                __half hx, lx, hy, ly;
                hsplit(x.x, hx, lx);
                hsplit(x.y, hy, ly);
                int reg = rr + hh * 2;
                Ah[kt][reg] = pack2(hx, hy);
                Al[kt][reg] = pack2(lx, ly);
            }
        }
    }

    float oA[8][4];
#pragma unroll
    for (int jd = 0; jd < 8; ++jd)
#pragma unroll
        for (int i = 0; i < 4; ++i) oA[jd][i] = 0.f;

    float mrun0 = -1e30f, mrun1 = -1e30f, lrun0 = 0.f, lrun1 = 0.f;

    const float* kb0 = k + (size_t)bh * S_ * D_;
    const float* vb0 = v + (size_t)bh * S_ * D_;
    const float* mbase = mask + (size_t)b * S_ * S_ + (size_t)qrow * S_;

    const float L2E = 1.4426950408889634f;

    const int ld_row = tid >> 4;          // 0..7 (+8 per iter step)
    const int ld_c4  = (tid & 15) * 4;    // d col

    // ---- tile loader: gmem fp32 -> smem fp16 hi/lo (K) + fp16 row-major (V) ----
    auto load_tile = [&](int jb, int buf) {
        const float* kb = kb0 + (size_t)jb * BN * D_;
        const float* vb = vb0 + (size_t)jb * BN * D_;
#pragma unroll
        for (int i = 0; i < 8; ++i) {
            int row = ld_row + i * 8;
            const float4 kx = *reinterpret_cast<const float4*>(kb + row * D_ + ld_c4);
            const float4 vx = *reinterpret_cast<const float4*>(vb + row * D_ + ld_c4);

            __half h0, l0, h1, l1, h2, l2, h3, l3;
            hsplit(kx.x, h0, l0); hsplit(kx.y, h1, l1);
            hsplit(kx.z, h2, l2); hsplit(kx.w, h3, l3);

            uint2 khv = make_uint2(pack2(h0, h1), pack2(h2, h3));
            uint2 klv = make_uint2(pack2(l0, l1), pack2(l2, l3));
            uint2 vv  = make_uint2(pack2(__float2half_rn(vx.x), __float2half_rn(vx.y)),
                                   pack2(__float2half_rn(vx.z), __float2half_rn(vx.w)));

            uint32_t akh = swaddr(khb[buf], row, ld_c4 * 2);
            uint32_t akl = swaddr(klb[buf], row, ld_c4 * 2);
            uint32_t av  = swaddr(vrb[buf], row, ld_c4 * 2);
            asm volatile("st.shared.v2.u32 [%0], {%1,%2};" :: "r"(akh), "r"(khv.x), "r"(khv.y));
            asm volatile("st.shared.v2.u32 [%0], {%1,%2};" :: "r"(akl), "r"(klv.x), "r"(klv.y));
            asm volatile("st.shared.v2.u32 [%0], {%1,%2};" :: "r"(av),  "r"(vv.x),  "r"(vv.y));
        }
    };

    load_tile(0, 0);
    __syncthreads();

    for (int jb = 0; jb < NT; ++jb) {
        const int buf = jb & 1;

        // ---- S = Q K^T : 3-term fp16 split, ldmatrix operands ----
        float sA[8][4];
#pragma unroll
        for (int j8 = 0; j8 < 8; ++j8)
#pragma unroll
            for (int i = 0; i < 4; ++i) sA[j8][i] = 0.f;

#pragma unroll
        for (int kt = 0; kt < 4; ++kt) {
            uint32_t bfr[16];
#pragma unroll
            for (int nb = 0; nb < 4; ++nb)
                ldm_x4(&bfr[nb * 4], kaddr(khb[buf], nb * 16, kt * 16, lane));
#pragma unroll
            for (int j8 = 0; j8 < 8; ++j8) {
                int off = (j8 >> 1) * 4 + (j8 & 1) * 2;
                mma16816(sA[j8], Ah[kt], bfr[off], bfr[off + 1]);
                mma16816(sA[j8], Al[kt], bfr[off], bfr[off + 1]);
            }
#pragma unroll
            for (int nb = 0; nb < 4; ++nb)
                ldm_x4(&bfr[nb * 4], kaddr(klb[buf], nb * 16, kt * 16, lane));
#pragma unroll
            for (int j8 = 0; j8 < 8; ++j8) {
                int off = (j8 >> 1) * 4 + (j8 & 1) * 2;
                mma16816(sA[j8], Ah[kt], bfr[off], bfr[off + 1]);
            }
        }

        // ---- additive mask ----
        const float* m0p = mbase + (size_t)jb * BN;
#pragma unroll
        for (int j8 = 0; j8 < 8; ++j8) {
            float2 m0 = *reinterpret_cast<const float2*>(m0p + j8 * 8 + 2 * t);
            float2 m1 = *reinterpret_cast<const float2*>(m0p + (size_t)8 * S_ + j8 * 8 + 2 * t);
            sA[j8][0] += m0.x; sA[j8][1] += m0.y;
            sA[j8][2] += m1.x; sA[j8][3] += m1.y;
        }

        // ---- online softmax ----
        float rm0 = -1e30f, rm1 = -1e30f;
#pragma unroll
        for (int j8 = 0; j8 < 8; ++j8) {
            rm0 = fmaxf(rm0, fmaxf(sA[j8][0], sA[j8][1]));
            rm1 = fmaxf(rm1, fmaxf(sA[j8][2], sA[j8][3]));
        }
        rm0 = fmaxf(rm0, __shfl_xor_sync(0xffffffffu, rm0, 1));
        rm0 = fmaxf(rm0, __shfl_xor_sync(0xffffffffu, rm0, 2));
        rm1 = fmaxf(rm1, __shfl_xor_sync(0xffffffffu, rm1, 1));
        rm1 = fmaxf(rm1, __shfl_xor_sync(0xffffffffu, rm1, 2));

        float mn0 = fmaxf(mrun0, rm0), mn1 = fmaxf(mrun1, rm1);
        float al0 = ex2f((mrun0 - mn0) * L2E);
        float al1 = ex2f((mrun1 - mn1) * L2E);
        mrun0 = mn0; mrun1 = mn1;

        float rs0 = 0.f, rs1 = 0.f;
        uint32_t Pa[4][4];
#pragma unroll
        for (int j8 = 0; j8 < 8; ++j8) {
            float p0 = ex2f((sA[j8][0] - mn0) * L2E);
            float p1 = ex2f((sA[j8][1] - mn0) * L2E);
            float p2 = ex2f((sA[j8][2] - mn1) * L2E);
            float p3 = ex2f((sA[j8][3] - mn1) * L2E);
            rs0 += p0 + p1;
            rs1 += p2 + p3;
            Pa[j8 >> 1][(j8 & 1) * 2 + 0] = pack2(__float2half_rn(p0), __float2half_rn(p1));
            Pa[j8 >> 1][(j8 & 1) * 2 + 1] = pack2(__float2half_rn(p2), __float2half_rn(p3));
        }
        rs0 += __shfl_xor_sync(0xffffffffu, rs0, 1);
        rs0 += __shfl_xor_sync(0xffffffffu, rs0, 2);
        rs1 += __shfl_xor_sync(0xffffffffu, rs1, 1);
        rs1 += __shfl_xor_sync(0xffffffffu, rs1, 2);
        lrun0 = lrun0 * al0 + rs0;
        lrun1 = lrun1 * al1 + rs1;

#pragma unroll
        for (int jd = 0; jd < 8; ++jd) {
            oA[jd][0] *= al0; oA[jd][1] *= al0;
            oA[jd][2] *= al1; oA[jd][3] *= al1;
        }

        // ---- O += P V : V row-major, ldmatrix.trans operands ----
#pragma unroll
        for (int kt2 = 0; kt2 < 4; ++kt2) {
            uint32_t bv[16];
#pragma unroll
            for (int db = 0; db < 4; ++db)
                ldm_x4_t(&bv[db * 4], vaddr(vrb[buf], kt2 * 16, db * 16, lane));
#pragma unroll
            for (int jd = 0; jd < 8; ++jd) {
                int off = (jd >> 1) * 4 + (jd & 1) * 2;
                mma16816(oA[jd], Pa[kt2], bv[off], bv[off + 1]);
            }
        }

        // ---- prefetch next tile into other buffer ----
        if (jb + 1 < NT) load_tile(jb + 1, buf ^ 1);
        __syncthreads();
    }

    // ---- epilogue ----
    float i0 = 1.f / lrun0, i1 = 1.f / lrun1;
    float* obase = out + ((size_t)bh * S_ + qrow) * D_;
#pragma unroll
    for (int jd = 0; jd < 8; ++jd) {
        float2 w0, w1;
        w0.x = oA[jd][0] * i0; w0.y = oA[jd][1] * i0;
        w1.x = oA[jd][2] * i1; w1.y = oA[jd][3] * i1;
        *reinterpret_cast<float2*>(obase + jd * 8 + 2 * t) = w0;
        *reinterpret_cast<float2*>(obase + (size_t)8 * D_ + jd * 8 + 2 * t) = w1;
    }
}

extern "C" void kernel_launch(void* const* d_in, const int* in_sizes, int n_in,
                              void* d_out, int out_size) {
    (void)in_sizes; (void)n_in; (void)out_size;
    const float* q    = (const float*)d_in[0];
    const float* k    = (const float*)d_in[1];
    const float* v    = (const float*)d_in[2];
    const float* mask = (const float*)d_in[3];
    dim3 grid(B_ * H_, S_ / BM);
    fa_kernel<<<grid, 128>>>(q, k, v, mask, (float*)d_out);
}